// round 1
// baseline (speedup 1.0000x reference)
#include <cuda_runtime.h>
#include <cstdint>
#include <cstddef>

#define N_NODES 20000
#define N_EDGES 40000
#define H 64
#define F_ATOM 62
#define F_BOND 6
#define B_GRAPH 512

// ---------------- device scratch (static: no allocation allowed) ----------------
__device__ float g_h[N_NODES * H];                    // node hidden state (ping-ponged in place)
__device__ float g_mlp[N_EDGES * H];                  // relu(edge_features @ Wm + bm)
__device__ float g_Ew3[H * H * H];                    // Ew transposed: Ew3[k][j*64+i] = Ew[k][i*64+j]
__device__ float g_AT[(size_t)N_EDGES * H * H];       // A^T per edge: AT[e][j*64+i] = A[e,i,j]  (655 MB)
__device__ float g_msg[N_NODES * H];                  // scatter-add message buffer
__device__ float g_gsum[B_GRAPH * H];                 // per-graph segment sum

// ---------------- f32x2 packed-FMA helpers (sm_100+) ----------------
typedef unsigned long long ull;
__device__ __forceinline__ ull pack2(float a, float b) {
    ull r; asm("mov.b64 %0,{%1,%2};" : "=l"(r) : "f"(a), "f"(b)); return r;
}
__device__ __forceinline__ void unpack2(ull v, float& a, float& b) {
    asm("mov.b64 {%0,%1},%2;" : "=f"(a), "=f"(b) : "l"(v));
}
__device__ __forceinline__ ull ffma2(ull a, ull b, ull c) {
    ull d; asm("fma.rn.f32x2 %0,%1,%2,%3;" : "=l"(d) : "l"(a), "l"(b), "l"(c)); return d;
}

__device__ __forceinline__ float selu_f(float x) {
    const float alpha = 1.6732632423543772f;
    const float scale = 1.0507009873554805f;
    return scale * (x > 0.f ? x : alpha * expm1f(x));
}

// ---------------- tiny prep kernels ----------------
__global__ void k_init_h(const float* __restrict__ nf) {
    int idx = blockIdx.x * 256 + threadIdx.x;
    if (idx >= N_NODES * H) return;
    int n = idx >> 6, c = idx & 63;
    g_h[idx] = (c < F_ATOM) ? nf[n * F_ATOM + c] : 0.f;
}

__global__ void k_mlp(const float* __restrict__ ef, const float* __restrict__ Wm,
                      const float* __restrict__ bm) {
    int idx = blockIdx.x * 256 + threadIdx.x;
    if (idx >= N_EDGES * H) return;
    int e = idx >> 6, c = idx & 63;
    float y = bm[c];
#pragma unroll
    for (int k = 0; k < F_BOND; k++) y = fmaf(ef[e * F_BOND + k], Wm[k * H + c], y);
    g_mlp[idx] = fmaxf(y, 0.f);
}

__global__ void k_transpose_ew(const float* __restrict__ Ew) {
    int idx = blockIdx.x * 256 + threadIdx.x;   // < 64*4096
    if (idx >= H * H * H) return;
    int k = idx >> 12;
    int c = idx & 4095;
    int j = c >> 6, i = c & 63;
    g_Ew3[idx] = Ew[(k << 12) + (i << 6) + j];
}

__global__ void k_zero_msg() {
    int idx = blockIdx.x * 256 + threadIdx.x;
    if (idx < N_NODES * H) g_msg[idx] = 0.f;
}
__global__ void k_zero_gsum() {
    int idx = blockIdx.x * 256 + threadIdx.x;
    if (idx < B_GRAPH * H) g_gsum[idx] = 0.f;
}

// ---------------- big GEMM: AT = mlp @ Ew3  (M=40000, N=4096, K=64) ----------------
// Tile: 64 edges x 128 cols per block, 256 threads, each thread = 8 edges x 4 cols.
// Warp = one edge-group (a-reads are smem broadcasts), lanes span cols (b-reads LDS.128).
__global__ void __launch_bounds__(256, 4) k_gemmA() {
    __shared__ float s_a[64 * 64];    // [e][k]   16 KB
    __shared__ float s_b[64 * 128];   // [k][c]   32 KB
    int t = threadIdx.x;
    int e0 = blockIdx.y * 64;
    int c0 = blockIdx.x * 128;

    for (int idx = t; idx < 64 * 64; idx += 256)
        s_a[idx] = g_mlp[e0 * 64 + idx];
    for (int idx = t; idx < 64 * 128; idx += 256) {
        int k = idx >> 7, c = idx & 127;
        s_b[idx] = g_Ew3[k * 4096 + c0 + c];
    }
    __syncthreads();

    int cg = t & 31;        // col group -> 4 cols
    int wg = t >> 5;        // warp id   -> 8 edges
    int col = cg * 4;
    int eb = wg * 8;

    ull acc[8][2];
#pragma unroll
    for (int e = 0; e < 8; e++) { acc[e][0] = 0ull; acc[e][1] = 0ull; }

#pragma unroll 4
    for (int k4 = 0; k4 < 64; k4 += 4) {
        float4 b0 = *(const float4*)&s_b[(k4 + 0) * 128 + col];
        float4 b1 = *(const float4*)&s_b[(k4 + 1) * 128 + col];
        float4 b2 = *(const float4*)&s_b[(k4 + 2) * 128 + col];
        float4 b3 = *(const float4*)&s_b[(k4 + 3) * 128 + col];
        ull b0l = pack2(b0.x, b0.y), b0h = pack2(b0.z, b0.w);
        ull b1l = pack2(b1.x, b1.y), b1h = pack2(b1.z, b1.w);
        ull b2l = pack2(b2.x, b2.y), b2h = pack2(b2.z, b2.w);
        ull b3l = pack2(b3.x, b3.y), b3h = pack2(b3.z, b3.w);
#pragma unroll
        for (int e = 0; e < 8; e++) {
            float4 a4 = *(const float4*)&s_a[(eb + e) * 64 + k4];
            ull a0 = pack2(a4.x, a4.x);
            ull a1 = pack2(a4.y, a4.y);
            ull a2 = pack2(a4.z, a4.z);
            ull a3 = pack2(a4.w, a4.w);
            acc[e][0] = ffma2(a0, b0l, acc[e][0]); acc[e][1] = ffma2(a0, b0h, acc[e][1]);
            acc[e][0] = ffma2(a1, b1l, acc[e][0]); acc[e][1] = ffma2(a1, b1h, acc[e][1]);
            acc[e][0] = ffma2(a2, b2l, acc[e][0]); acc[e][1] = ffma2(a2, b2h, acc[e][1]);
            acc[e][0] = ffma2(a3, b3l, acc[e][0]); acc[e][1] = ffma2(a3, b3h, acc[e][1]);
        }
    }

#pragma unroll
    for (int e = 0; e < 8; e++) {
        float x0, x1, x2, x3;
        unpack2(acc[e][0], x0, x1);
        unpack2(acc[e][1], x2, x3);
        float4 o; o.x = x0; o.y = x1; o.z = x2; o.w = x3;
        *(float4*)&g_AT[(size_t)(e0 + eb + e) * 4096 + c0 + col] = o;
    }
}

// ---------------- per-step bmm + scatter: msg[dom[e]] += A_e @ h[range[e]] ----------------
// 1 warp per edge (lane handles 2 output dims via float2); 8 edges per block.
__global__ void __launch_bounds__(256) k_bmm(const int* __restrict__ erange,
                                             const int* __restrict__ edom) {
    __shared__ float s_hj[8][64];
    int w = threadIdx.x >> 5;
    int lane = threadIdx.x & 31;
    int e = blockIdx.x * 8 + w;

    int r = erange[e];
    float2 hv = *(const float2*)&g_h[r * 64 + lane * 2];
    s_hj[w][lane * 2]     = hv.x;
    s_hj[w][lane * 2 + 1] = hv.y;
    __syncwarp();

    const float* Ae = g_AT + (size_t)e * 4096;
    float y0 = 0.f, y1 = 0.f;
#pragma unroll 16
    for (int j = 0; j < 64; j++) {
        float2 a = *(const float2*)&Ae[j * 64 + lane * 2];
        float hj = s_hj[w][j];
        y0 = fmaf(a.x, hj, y0);
        y1 = fmaf(a.y, hj, y1);
    }
    int d = edom[e];
    atomicAdd(&g_msg[d * 64 + lane * 2],     y0);
    atomicAdd(&g_msg[d * 64 + lane * 2 + 1], y1);
}

// ---------------- node update: h = selu(msg @ Wu + bu + h) ----------------
__global__ void __launch_bounds__(256) k_update(const float* __restrict__ Wu,
                                                const float* __restrict__ bu) {
    __shared__ float s_w[64 * 64];     // 16 KB
    __shared__ float s_m[16 * 64];     // 4 KB
    int t = threadIdx.x;
    int n0 = blockIdx.x * 16;
    for (int idx = t; idx < 4096; idx += 256) s_w[idx] = Wu[idx];
    for (int idx = t; idx < 1024; idx += 256) s_m[idx] = g_msg[n0 * 64 + idx];
    __syncthreads();

    int i = t & 63;
    int bg = t >> 6;
    float bv = bu[i];
#pragma unroll
    for (int rep = 0; rep < 4; rep++) {
        int nn = bg * 4 + rep;
        int n = n0 + nn;
        float y = bv + g_h[n * 64 + i];
#pragma unroll
        for (int k = 0; k < 64; k++) y = fmaf(s_m[nn * 64 + k], s_w[k * 64 + i], y);
        g_h[n * 64 + i] = selu_f(y);
    }
}

// ---------------- embed + readout activation + graph segment-sum ----------------
__global__ void __launch_bounds__(256) k_embed_act(const float* __restrict__ Wae,
                                                   const float* __restrict__ bae,
                                                   const float* __restrict__ WR,
                                                   const float* __restrict__ bR,
                                                   const int* __restrict__ gid) {
    __shared__ float s_w1[4096];   // Wae 16 KB
    __shared__ float s_w2[4096];   // WR  16 KB
    __shared__ float s_h[1024];    // 16 nodes x 64
    __shared__ float s_ae[1024];
    int t = threadIdx.x;
    int n0 = blockIdx.x * 16;
    for (int idx = t; idx < 4096; idx += 256) { s_w1[idx] = Wae[idx]; s_w2[idx] = WR[idx]; }
    for (int idx = t; idx < 1024; idx += 256) s_h[idx] = g_h[n0 * 64 + idx];
    __syncthreads();

    int i = t & 63;
    int bg = t >> 6;
    float b1 = bae[i];
#pragma unroll
    for (int rep = 0; rep < 4; rep++) {
        int nn = bg * 4 + rep;
        float y = b1;
#pragma unroll
        for (int k = 0; k < 64; k++) y = fmaf(s_h[nn * 64 + k], s_w1[k * 64 + i], y);
        s_ae[nn * 64 + i] = y;
    }
    __syncthreads();

    float b2 = bR[i];
#pragma unroll
    for (int rep = 0; rep < 4; rep++) {
        int nn = bg * 4 + rep;
        float y = b2;
#pragma unroll
        for (int k = 0; k < 64; k++) y = fmaf(s_ae[nn * 64 + k], s_w2[k * 64 + i], y);
        float act = selu_f(y);
        int g = gid[n0 + nn];
        atomicAdd(&g_gsum[g * 64 + i], act);
    }
}

// ---------------- head: out[b] = relu(tanh(gsum[b]) @ Wmlp + bmlp) @ Wout + bout ----------------
__global__ void k_head(const float* __restrict__ Wmlp, const float* __restrict__ bmlp,
                       const float* __restrict__ Wout, const float* __restrict__ bout,
                       float* __restrict__ out) {
    __shared__ float s_ge[64];
    __shared__ float s_mo[64];
    int b = blockIdx.x, t = threadIdx.x;   // 64 threads
    s_ge[t] = tanhf(g_gsum[b * 64 + t]);
    __syncthreads();
    float y = bmlp[t];
#pragma unroll
    for (int k = 0; k < 64; k++) y = fmaf(s_ge[k], Wmlp[k * 64 + t], y);
    s_mo[t] = fmaxf(y, 0.f) * Wout[t];
    __syncthreads();
    if (t < 32) {
        float v = s_mo[t] + s_mo[t + 32];
#pragma unroll
        for (int o = 16; o > 0; o >>= 1) v += __shfl_down_sync(0xffffffffu, v, o);
        if (t == 0) out[b] = v + bout[0];
    }
}

// ---------------- launch ----------------
extern "C" void kernel_launch(void* const* d_in, const int* in_sizes, int n_in,
                              void* d_out, int out_size) {
    (void)in_sizes; (void)n_in; (void)out_size;
    const float* nf    = (const float*)d_in[0];
    const float* ef    = (const float*)d_in[1];
    const int*   edom  = (const int*)d_in[2];
    const int*   erng  = (const int*)d_in[3];
    const int*   gid   = (const int*)d_in[4];
    const float* Wm    = (const float*)d_in[5];
    const float* bm    = (const float*)d_in[6];
    const float* Ew    = (const float*)d_in[7];
    const float* Wu0   = (const float*)d_in[8];
    const float* bu0   = (const float*)d_in[9];
    const float* Wu1   = (const float*)d_in[10];
    const float* bu1   = (const float*)d_in[11];
    const float* Wae   = (const float*)d_in[12];
    const float* bae   = (const float*)d_in[13];
    const float* WR    = (const float*)d_in[14];
    const float* bR    = (const float*)d_in[15];
    const float* Wmlp  = (const float*)d_in[16];
    const float* bmlp  = (const float*)d_in[17];
    const float* Wout  = (const float*)d_in[18];
    const float* bout  = (const float*)d_in[19];
    float* out = (float*)d_out;

    // prep
    k_init_h<<<(N_NODES * H + 255) / 256, 256>>>(nf);
    k_mlp<<<(N_EDGES * H + 255) / 256, 256>>>(ef, Wm, bm);
    k_transpose_ew<<<(H * H * H + 255) / 256, 256>>>(Ew);

    // A^T = mlp @ Ew3   (computed once; edge features are T-invariant)
    dim3 gA(4096 / 128, N_EDGES / 64);
    k_gemmA<<<gA, 256>>>();

    // two message-passing steps
    k_zero_msg<<<(N_NODES * H + 255) / 256, 256>>>();
    k_bmm<<<N_EDGES / 8, 256>>>(erng, edom);
    k_update<<<N_NODES / 16, 256>>>(Wu0, bu0);

    k_zero_msg<<<(N_NODES * H + 255) / 256, 256>>>();
    k_bmm<<<N_EDGES / 8, 256>>>(erng, edom);
    k_update<<<N_NODES / 16, 256>>>(Wu1, bu1);

    // readout
    k_zero_gsum<<<(B_GRAPH * H + 255) / 256, 256>>>();
    k_embed_act<<<N_NODES / 16, 256>>>(Wae, bae, WR, bR, gid);
    k_head<<<B_GRAPH, 64>>>(Wmlp, bmlp, Wout, bout, out);
}

// round 9
// speedup vs baseline: 1.4863x; 1.4863x over previous
#include <cuda_runtime.h>
#include <cuda_bf16.h>
#include <cstdint>
#include <cstddef>

#define N_NODES 20000
#define N_EDGES 40000
#define H 64
#define F_ATOM 62
#define F_BOND 6
#define B_GRAPH 512

#define N_TILES 313      // ceil(40000 / 128) edge tiles
#define CHUNKS 32        // K = 4096 split into 32 chunks of 128

// ---------------- k_msg smem layout (bytes) ----------------
// ed/er: 128 ints each; hj: 128 rows x 72 floats; mlp_t: 64 x 129 floats (transposed);
// w: one 32KB chunk of pre-packed B-fragments.
#define S2_ED    0
#define S2_ER    512
#define S2_HJ    1024
#define S2_MLP   (1024 + 128*72*4)             // 37888
#define S2_W     (S2_MLP + 64*129*4)           // 70912 (16B aligned)
#define S2_TOTAL (S2_W + 32768)                // 103680

// ---------------- device scratch ----------------
__device__ float g_h[N_NODES * H];
__device__ float g_mlp[N_EDGES * H];
__device__ float g_msg[N_NODES * H];
__device__ float g_gsum[B_GRAPH * H];
// W pre-packed into HMMA B-fragment layout:
// index [c][s][nt][lane] -> uint4 {Whi_reg0, Whi_reg1, Wlo_reg0, Wlo_reg1}
// where W2[(k*64+j), i] = Ew[k, i*64+j], k = 2c + (s>>2), j0 = (s&3)*16,
// B-frag: reg0 = {W[K0,n], W[K0+1,n]}, reg1 = {W[K0+8,n], W[K0+9,n]},
// K0 = j0 + (lane&3)*2, n = nt*8 + lane>>2.
__device__ uint4 g_Wp[CHUNKS * 8 * 8 * 32];    // 1 MB

// ---------------- helpers ----------------
__device__ __forceinline__ uint32_t pack_bf(float lo, float hi) {
    __nv_bfloat162 t = __floats2bfloat162_rn(lo, hi);   // x=lo half, y=hi half
    return *(uint32_t*)&t;
}
__device__ __forceinline__ float bf_lo_f32(uint32_t p) { return __uint_as_float(p << 16); }
__device__ __forceinline__ float bf_hi_f32(uint32_t p) { return __uint_as_float(p & 0xFFFF0000u); }

__device__ __forceinline__ void mma_bf16(float* d, const uint32_t* a, uint32_t b0, uint32_t b1) {
    asm volatile(
        "mma.sync.aligned.m16n8k16.row.col.f32.bf16.bf16.f32 "
        "{%0,%1,%2,%3}, {%4,%5,%6,%7}, {%8,%9}, {%0,%1,%2,%3};"
        : "+f"(d[0]), "+f"(d[1]), "+f"(d[2]), "+f"(d[3])
        : "r"(a[0]), "r"(a[1]), "r"(a[2]), "r"(a[3]), "r"(b0), "r"(b1));
}

__device__ __forceinline__ float selu_f(float x) {
    const float alpha = 1.6732632423543772f;
    const float scale = 1.0507009873554805f;
    return scale * (x > 0.f ? x : alpha * expm1f(x));
}

// ---------------- prep kernels ----------------
__global__ void k_init_h(const float* __restrict__ nf) {
    int idx = blockIdx.x * 256 + threadIdx.x;
    if (idx >= N_NODES * H) return;
    int n = idx >> 6, c = idx & 63;
    g_h[idx] = (c < F_ATOM) ? nf[n * F_ATOM + c] : 0.f;
}

__global__ void k_mlp(const float* __restrict__ ef, const float* __restrict__ Wm,
                      const float* __restrict__ bm) {
    int idx = blockIdx.x * 256 + threadIdx.x;
    if (idx >= N_EDGES * H) return;
    int e = idx >> 6, c = idx & 63;
    float y = bm[c];
#pragma unroll
    for (int k = 0; k < F_BOND; k++) y = fmaf(ef[e * F_BOND + k], Wm[k * H + c], y);
    g_mlp[idx] = fmaxf(y, 0.f);
}

// Pack Ew into B-fragment layout (hi/lo bf16 split).
__global__ void k_prep_wpack(const float* __restrict__ Ew) {
    int idx = blockIdx.x * 256 + threadIdx.x;
    if (idx >= CHUNKS * 8 * 8 * 32) return;
    int lane = idx & 31;
    int nt   = (idx >> 5) & 7;
    int s    = (idx >> 8) & 7;
    int c    = idx >> 11;
    int k  = 2 * c + (s >> 2);
    int j0 = (s & 3) * 16;
    int n  = nt * 8 + (lane >> 2);
    int K0 = j0 + (lane & 3) * 2;
    const float* base = Ew + k * 4096 + n * 64;
    float v0 = base[K0 + 0];
    float v1 = base[K0 + 1];
    float v8 = base[K0 + 8];
    float v9 = base[K0 + 9];
    uint32_t h0 = pack_bf(v0, v1);
    uint32_t h1 = pack_bf(v8, v9);
    uint32_t l0 = pack_bf(v0 - bf_lo_f32(h0), v1 - bf_hi_f32(h0));
    uint32_t l1 = pack_bf(v8 - bf_lo_f32(h1), v9 - bf_hi_f32(h1));
    uint4 w; w.x = h0; w.y = h1; w.z = l0; w.w = l1;
    g_Wp[idx] = w;
}

__global__ void k_zero_msg() {
    int idx = blockIdx.x * 256 + threadIdx.x;
    if (idx < N_NODES * H) g_msg[idx] = 0.f;
}
__global__ void k_zero_gsum() {
    int idx = blockIdx.x * 256 + threadIdx.x;
    if (idx < B_GRAPH * H) g_gsum[idx] = 0.f;
}

// ---------------- fused message kernel (warp-level bf16 MMA, 3-way hi/lo split) ----
// One CTA = 128 edges, 8 warps; warp w owns rows [16w, 16w+16).
// G[e,i] = sum_{k,j} mlp[e,k]*hj[e,j]*Ew[k,i*64+j]
//        = P[128 x 4096] @ W2[4096 x 64], P generated directly in A-fragment regs.
__global__ void __launch_bounds__(256, 2) k_msg(const int* __restrict__ erng,
                                                const int* __restrict__ edom) {
    extern __shared__ char smem[];
    int t = threadIdx.x, wid = t >> 5, lane = t & 31;
    int e0 = blockIdx.x * 128;

    int* ed_s = (int*)(smem + S2_ED);
    int* er_s = (int*)(smem + S2_ER);
    float* hj_s = (float*)(smem + S2_HJ);     // stride 72
    float* mlp_t = (float*)(smem + S2_MLP);   // [k][row], stride 129
    uint4* w_s = (uint4*)(smem + S2_W);       // [s][nt][lane]

    if (t < 128) {
        int e = e0 + t;
        er_s[t] = (e < N_EDGES) ? erng[e] : -1;
        ed_s[t] = (e < N_EDGES) ? edom[e] : -1;
    }
    __syncthreads();

    // gather hj = h[erange[e]] (zeros for padded edges)
    for (int idx = t; idx < 128 * 16; idx += 256) {
        int r = idx >> 4, q = idx & 15;
        int src = er_s[r];
        float4 v = make_float4(0.f, 0.f, 0.f, 0.f);
        if (src >= 0) v = *(const float4*)&g_h[src * 64 + q * 4];
        *(float4*)&hj_s[r * 72 + q * 4] = v;
    }
    // mlp transposed: mlp_t[k][row]
    for (int idx = t; idx < 128 * 64; idx += 256) {
        int k = idx & 63, r = idx >> 6;
        float v = (e0 + r < N_EDGES) ? g_mlp[(e0 + r) * 64 + k] : 0.f;
        mlp_t[k * 129 + r] = v;
    }

    float acc[8][4];
#pragma unroll
    for (int nt = 0; nt < 8; nt++) { acc[nt][0] = acc[nt][1] = acc[nt][2] = acc[nt][3] = 0.f; }

    // prefetch W chunk 0 (32 KB / 256 threads = 8 uint4 each)
    uint4 rW[8];
#pragma unroll
    for (int q = 0; q < 8; q++) rW[q] = g_Wp[t + 256 * q];

    int row0 = wid * 16 + (lane >> 2);
    int jc   = (lane & 3) * 2;
    const float* hj0 = hj_s + row0 * 72;
    const float* hj1 = hj_s + (row0 + 8) * 72;

    for (int c = 0; c < CHUNKS; c++) {
        __syncthreads();   // prior chunk's w_s reads complete
#pragma unroll
        for (int q = 0; q < 8; q++) w_s[t + 256 * q] = rW[q];
        __syncthreads();   // w_s visible

        if (c + 1 < CHUNKS) {
#pragma unroll
            for (int q = 0; q < 8; q++) rW[q] = g_Wp[(c + 1) * 2048 + t + 256 * q];
        }

#pragma unroll
        for (int s = 0; s < 8; s++) {
            int k = 2 * c + (s >> 2);
            int j0 = (s & 3) * 16;
            float mv0 = mlp_t[k * 129 + row0];
            float mv1 = mlp_t[k * 129 + row0 + 8];
            float2 h00 = *(const float2*)(hj0 + j0 + jc);
            float2 h01 = *(const float2*)(hj0 + j0 + jc + 8);
            float2 h10 = *(const float2*)(hj1 + j0 + jc);
            float2 h11 = *(const float2*)(hj1 + j0 + jc + 8);

            float p00 = mv0 * h00.x, p01 = mv0 * h00.y;   // a0: row0, cols jc, jc+1
            float p10 = mv1 * h10.x, p11 = mv1 * h10.y;   // a1: row0+8
            float p20 = mv0 * h01.x, p21 = mv0 * h01.y;   // a2: row0, cols +8
            float p30 = mv1 * h11.x, p31 = mv1 * h11.y;   // a3: row0+8, cols +8

            uint32_t ahi[4], alo[4];
            ahi[0] = pack_bf(p00, p01);
            ahi[1] = pack_bf(p10, p11);
            ahi[2] = pack_bf(p20, p21);
            ahi[3] = pack_bf(p30, p31);
            alo[0] = pack_bf(p00 - bf_lo_f32(ahi[0]), p01 - bf_hi_f32(ahi[0]));
            alo[1] = pack_bf(p10 - bf_lo_f32(ahi[1]), p11 - bf_hi_f32(ahi[1]));
            alo[2] = pack_bf(p20 - bf_lo_f32(ahi[2]), p21 - bf_hi_f32(ahi[2]));
            alo[3] = pack_bf(p30 - bf_lo_f32(ahi[3]), p31 - bf_hi_f32(ahi[3]));

#pragma unroll
            for (int nt = 0; nt < 8; nt++) {
                uint4 w = w_s[(s * 8 + nt) * 32 + lane];   // LDS.128
                mma_bf16(acc[nt], ahi, w.x, w.y);          // Phi * Whi
                mma_bf16(acc[nt], alo, w.x, w.y);          // Plo * Whi
                mma_bf16(acc[nt], ahi, w.z, w.w);          // Phi * Wlo
            }
        }
    }

    // epilogue: scatter-add accumulators into g_msg
    int d0 = ed_s[row0];
    int d1 = ed_s[row0 + 8];
#pragma unroll
    for (int nt = 0; nt < 8; nt++) {
        int col = nt * 8 + jc;
        if (d0 >= 0) {
            atomicAdd(&g_msg[d0 * 64 + col],     acc[nt][0]);
            atomicAdd(&g_msg[d0 * 64 + col + 1], acc[nt][1]);
        }
        if (d1 >= 0) {
            atomicAdd(&g_msg[d1 * 64 + col],     acc[nt][2]);
            atomicAdd(&g_msg[d1 * 64 + col + 1], acc[nt][3]);
        }
    }
}

// ---------------- node update: h = selu(msg @ Wu + bu + h) ----------------
__global__ void __launch_bounds__(256) k_update(const float* __restrict__ Wu,
                                                const float* __restrict__ bu) {
    __shared__ float s_w[64 * 64];
    __shared__ float s_m[16 * 64];
    int t = threadIdx.x;
    int n0 = blockIdx.x * 16;
    for (int idx = t; idx < 4096; idx += 256) s_w[idx] = Wu[idx];
    for (int idx = t; idx < 1024; idx += 256) s_m[idx] = g_msg[n0 * 64 + idx];
    __syncthreads();

    int i = t & 63;
    int bg = t >> 6;
    float bv = bu[i];
#pragma unroll
    for (int rep = 0; rep < 4; rep++) {
        int nn = bg * 4 + rep;
        int n = n0 + nn;
        float y = bv + g_h[n * 64 + i];
#pragma unroll
        for (int k = 0; k < 64; k++) y = fmaf(s_m[nn * 64 + k], s_w[k * 64 + i], y);
        g_h[n * 64 + i] = selu_f(y);
    }
}

// ---------------- embed + readout activation + graph segment-sum ----------------
__global__ void __launch_bounds__(256) k_embed_act(const float* __restrict__ Wae,
                                                   const float* __restrict__ bae,
                                                   const float* __restrict__ WR,
                                                   const float* __restrict__ bR,
                                                   const int* __restrict__ gid) {
    __shared__ float s_w1[4096];
    __shared__ float s_w2[4096];
    __shared__ float s_h[1024];
    __shared__ float s_ae[1024];
    int t = threadIdx.x;
    int n0 = blockIdx.x * 16;
    for (int idx = t; idx < 4096; idx += 256) { s_w1[idx] = Wae[idx]; s_w2[idx] = WR[idx]; }
    for (int idx = t; idx < 1024; idx += 256) s_h[idx] = g_h[n0 * 64 + idx];
    __syncthreads();

    int i = t & 63;
    int bg = t >> 6;
    float b1 = bae[i];
#pragma unroll
    for (int rep = 0; rep < 4; rep++) {
        int nn = bg * 4 + rep;
        float y = b1;
#pragma unroll
        for (int k = 0; k < 64; k++) y = fmaf(s_h[nn * 64 + k], s_w1[k * 64 + i], y);
        s_ae[nn * 64 + i] = y;
    }
    __syncthreads();

    float b2 = bR[i];
#pragma unroll
    for (int rep = 0; rep < 4; rep++) {
        int nn = bg * 4 + rep;
        float y = b2;
#pragma unroll
        for (int k = 0; k < 64; k++) y = fmaf(s_ae[nn * 64 + k], s_w2[k * 64 + i], y);
        float act = selu_f(y);
        int g = gid[n0 + nn];
        atomicAdd(&g_gsum[g * 64 + i], act);
    }
}

// ---------------- head ----------------
__global__ void k_head(const float* __restrict__ Wmlp, const float* __restrict__ bmlp,
                       const float* __restrict__ Wout, const float* __restrict__ bout,
                       float* __restrict__ out) {
    __shared__ float s_ge[64];
    __shared__ float s_mo[64];
    int b = blockIdx.x, t = threadIdx.x;
    s_ge[t] = tanhf(g_gsum[b * 64 + t]);
    __syncthreads();
    float y = bmlp[t];
#pragma unroll
    for (int k = 0; k < 64; k++) y = fmaf(s_ge[k], Wmlp[k * 64 + t], y);
    s_mo[t] = fmaxf(y, 0.f) * Wout[t];
    __syncthreads();
    if (t < 32) {
        float v = s_mo[t] + s_mo[t + 32];
#pragma unroll
        for (int o = 16; o > 0; o >>= 1) v += __shfl_down_sync(0xffffffffu, v, o);
        if (t == 0) out[b] = v + bout[0];
    }
}

// ---------------- launch ----------------
extern "C" void kernel_launch(void* const* d_in, const int* in_sizes, int n_in,
                              void* d_out, int out_size) {
    (void)in_sizes; (void)n_in; (void)out_size;
    const float* nf    = (const float*)d_in[0];
    const float* ef    = (const float*)d_in[1];
    const int*   edom  = (const int*)d_in[2];
    const int*   erng  = (const int*)d_in[3];
    const int*   gid   = (const int*)d_in[4];
    const float* Wm    = (const float*)d_in[5];
    const float* bm    = (const float*)d_in[6];
    const float* Ew    = (const float*)d_in[7];
    const float* Wu0   = (const float*)d_in[8];
    const float* bu0   = (const float*)d_in[9];
    const float* Wu1   = (const float*)d_in[10];
    const float* bu1   = (const float*)d_in[11];
    const float* Wae   = (const float*)d_in[12];
    const float* bae   = (const float*)d_in[13];
    const float* WR    = (const float*)d_in[14];
    const float* bR    = (const float*)d_in[15];
    const float* Wmlp  = (const float*)d_in[16];
    const float* bmlp  = (const float*)d_in[17];
    const float* Wout  = (const float*)d_in[18];
    const float* bout  = (const float*)d_in[19];
    float* out = (float*)d_out;

    cudaFuncSetAttribute(k_msg, cudaFuncAttributeMaxDynamicSharedMemorySize, S2_TOTAL);

    // prep
    k_init_h<<<(N_NODES * H + 255) / 256, 256>>>(nf);
    k_mlp<<<(N_EDGES * H + 255) / 256, 256>>>(ef, Wm, bm);
    k_prep_wpack<<<(CHUNKS * 8 * 8 * 32 + 255) / 256, 256>>>(Ew);

    // message passing step 1
    k_zero_msg<<<(N_NODES * H + 255) / 256, 256>>>();
    k_msg<<<N_TILES, 256, S2_TOTAL>>>(erng, edom);
    k_update<<<N_NODES / 16, 256>>>(Wu0, bu0);

    // message passing step 2
    k_zero_msg<<<(N_NODES * H + 255) / 256, 256>>>();
    k_msg<<<N_TILES, 256, S2_TOTAL>>>(erng, edom);
    k_update<<<N_NODES / 16, 256>>>(Wu1, bu1);

    // readout
    k_zero_gsum<<<(B_GRAPH * H + 255) / 256, 256>>>();
    k_embed_act<<<N_NODES / 16, 256>>>(Wae, bae, WR, bR, gid);
    k_head<<<B_GRAPH, 64>>>(Wmlp, bmlp, Wout, bout, out);
}

// round 17
// speedup vs baseline: 2.7912x; 1.8779x over previous
#include <cuda_runtime.h>
#include <cuda_fp16.h>
#include <cstdint>
#include <cstddef>

#define N_NODES 20000
#define N_EDGES 40000
#define H 64
#define F_ATOM 62
#define F_BOND 6
#define B_GRAPH 512

#define N_TILES 313      // ceil(40000 / 128) edge tiles
#define CHUNKS 32        // K = 4096 split into 32 chunks of 128

// ---------------- k_msg smem layout (bytes) ----------------
// ed/er: 128 ints each; hj: 128 rows x 72 floats; mlp_t: 64 x 129 floats (transposed);
// w: one 16KB chunk of pre-packed fp16 B-fragments.
#define S2_ED    0
#define S2_ER    512
#define S2_HJ    1024
#define S2_MLP   (1024 + 128*72*4)             // 37888
#define S2_W     (S2_MLP + 64*129*4)           // 70912 (16B aligned)
#define S2_TOTAL (S2_W + 16384)                // 87296

// ---------------- device scratch ----------------
__device__ float g_h[N_NODES * H];
__device__ float g_mlp[N_EDGES * H];
__device__ float g_msg[N_NODES * H];
__device__ float g_gsum[B_GRAPH * H];
// W pre-packed into HMMA B-fragment layout (single fp16):
// index [c][s][nt][lane] -> uint2 {W_reg0, W_reg1}
// where W2[(k*64+j), i] = Ew[k, i*64+j], k = 2c + (s>>2), j0 = (s&3)*16,
// B-frag: reg0 = {W[K0,n], W[K0+1,n]}, reg1 = {W[K0+8,n], W[K0+9,n]},
// K0 = j0 + (lane&3)*2, n = nt*8 + lane>>2.
__device__ uint2 g_Wp[CHUNKS * 8 * 8 * 32];    // 512 KB

// ---------------- helpers ----------------
__device__ __forceinline__ uint32_t pack_h2(float lo, float hi) {
    __half2 t = __floats2half2_rn(lo, hi);   // x=lo half, y=hi half
    return *(uint32_t*)&t;
}

__device__ __forceinline__ void mma_f16(float* d, const uint32_t* a, uint32_t b0, uint32_t b1) {
    asm volatile(
        "mma.sync.aligned.m16n8k16.row.col.f32.f16.f16.f32 "
        "{%0,%1,%2,%3}, {%4,%5,%6,%7}, {%8,%9}, {%0,%1,%2,%3};"
        : "+f"(d[0]), "+f"(d[1]), "+f"(d[2]), "+f"(d[3])
        : "r"(a[0]), "r"(a[1]), "r"(a[2]), "r"(a[3]), "r"(b0), "r"(b1));
}

__device__ __forceinline__ float selu_f(float x) {
    const float alpha = 1.6732632423543772f;
    const float scale = 1.0507009873554805f;
    return scale * (x > 0.f ? x : alpha * expm1f(x));
}

// ---------------- prep kernels ----------------
__global__ void k_init_h(const float* __restrict__ nf) {
    int idx = blockIdx.x * 256 + threadIdx.x;
    if (idx >= N_NODES * H) return;
    int n = idx >> 6, c = idx & 63;
    g_h[idx] = (c < F_ATOM) ? nf[n * F_ATOM + c] : 0.f;
}

__global__ void k_mlp(const float* __restrict__ ef, const float* __restrict__ Wm,
                      const float* __restrict__ bm) {
    int idx = blockIdx.x * 256 + threadIdx.x;
    if (idx >= N_EDGES * H) return;
    int e = idx >> 6, c = idx & 63;
    float y = bm[c];
#pragma unroll
    for (int k = 0; k < F_BOND; k++) y = fmaf(ef[e * F_BOND + k], Wm[k * H + c], y);
    g_mlp[idx] = fmaxf(y, 0.f);
}

// Pack Ew into fp16 B-fragment layout.
__global__ void k_prep_wpack(const float* __restrict__ Ew) {
    int idx = blockIdx.x * 256 + threadIdx.x;
    if (idx >= CHUNKS * 8 * 8 * 32) return;
    int lane = idx & 31;
    int nt   = (idx >> 5) & 7;
    int s    = (idx >> 8) & 7;
    int c    = idx >> 11;
    int k  = 2 * c + (s >> 2);
    int j0 = (s & 3) * 16;
    int n  = nt * 8 + (lane >> 2);
    int K0 = j0 + (lane & 3) * 2;
    const float* base = Ew + k * 4096 + n * 64;
    uint2 w;
    w.x = pack_h2(base[K0 + 0], base[K0 + 1]);
    w.y = pack_h2(base[K0 + 8], base[K0 + 9]);
    g_Wp[idx] = w;
}

__global__ void k_zero_msg() {
    int idx = blockIdx.x * 256 + threadIdx.x;
    if (idx < N_NODES * H) g_msg[idx] = 0.f;
}
__global__ void k_zero_gsum() {
    int idx = blockIdx.x * 256 + threadIdx.x;
    if (idx < B_GRAPH * H) g_gsum[idx] = 0.f;
}

// ---------------- fused message kernel (warp-level fp16 MMA, single term) ----
// One CTA = 128 edges, 8 warps; warp w owns rows [16w, 16w+16).
// G[e,i] = sum_{k,j} mlp[e,k]*hj[e,j]*Ew[k,i*64+j]
//        = P[128 x 4096] @ W2[4096 x 64], P generated directly in A-fragment regs.
__global__ void __launch_bounds__(256, 2) k_msg(const int* __restrict__ erng,
                                                const int* __restrict__ edom) {
    extern __shared__ char smem[];
    int t = threadIdx.x, wid = t >> 5, lane = t & 31;
    int e0 = blockIdx.x * 128;

    int* ed_s = (int*)(smem + S2_ED);
    int* er_s = (int*)(smem + S2_ER);
    float* hj_s = (float*)(smem + S2_HJ);     // stride 72
    float* mlp_t = (float*)(smem + S2_MLP);   // [k][row], stride 129
    uint2* w_s = (uint2*)(smem + S2_W);       // [s][nt][lane]

    if (t < 128) {
        int e = e0 + t;
        er_s[t] = (e < N_EDGES) ? erng[e] : -1;
        ed_s[t] = (e < N_EDGES) ? edom[e] : -1;
    }
    __syncthreads();

    // gather hj = h[erange[e]] (zeros for padded edges)
    for (int idx = t; idx < 128 * 16; idx += 256) {
        int r = idx >> 4, q = idx & 15;
        int src = er_s[r];
        float4 v = make_float4(0.f, 0.f, 0.f, 0.f);
        if (src >= 0) v = *(const float4*)&g_h[src * 64 + q * 4];
        *(float4*)&hj_s[r * 72 + q * 4] = v;
    }
    // mlp transposed: mlp_t[k][row]
    for (int idx = t; idx < 128 * 64; idx += 256) {
        int k = idx & 63, r = idx >> 6;
        float v = (e0 + r < N_EDGES) ? g_mlp[(e0 + r) * 64 + k] : 0.f;
        mlp_t[k * 129 + r] = v;
    }

    float acc[8][4];
#pragma unroll
    for (int nt = 0; nt < 8; nt++) { acc[nt][0] = acc[nt][1] = acc[nt][2] = acc[nt][3] = 0.f; }

    // prefetch W chunk 0 (16 KB / 256 threads = 8 uint2 each)
    uint2 rW[8];
#pragma unroll
    for (int q = 0; q < 8; q++) rW[q] = g_Wp[t + 256 * q];

    int row0 = wid * 16 + (lane >> 2);
    int jc   = (lane & 3) * 2;
    const float* hj0 = hj_s + row0 * 72;
    const float* hj1 = hj_s + (row0 + 8) * 72;

    for (int c = 0; c < CHUNKS; c++) {
        __syncthreads();   // prior chunk's w_s reads complete
#pragma unroll
        for (int q = 0; q < 8; q++) w_s[t + 256 * q] = rW[q];
        __syncthreads();   // w_s visible

        if (c + 1 < CHUNKS) {
#pragma unroll
            for (int q = 0; q < 8; q++) rW[q] = g_Wp[(c + 1) * 2048 + t + 256 * q];
        }

#pragma unroll
        for (int s = 0; s < 8; s++) {
            int k = 2 * c + (s >> 2);
            int j0 = (s & 3) * 16;
            float mv0 = mlp_t[k * 129 + row0];
            float mv1 = mlp_t[k * 129 + row0 + 8];
            float2 h00 = *(const float2*)(hj0 + j0 + jc);
            float2 h01 = *(const float2*)(hj0 + j0 + jc + 8);
            float2 h10 = *(const float2*)(hj1 + j0 + jc);
            float2 h11 = *(const float2*)(hj1 + j0 + jc + 8);

            uint32_t a[4];
            a[0] = pack_h2(mv0 * h00.x, mv0 * h00.y);   // row0,   cols jc, jc+1
            a[1] = pack_h2(mv1 * h10.x, mv1 * h10.y);   // row0+8
            a[2] = pack_h2(mv0 * h01.x, mv0 * h01.y);   // row0,   cols +8
            a[3] = pack_h2(mv1 * h11.x, mv1 * h11.y);   // row0+8, cols +8

#pragma unroll
            for (int nt = 0; nt < 8; nt++) {
                uint2 w = w_s[(s * 8 + nt) * 32 + lane];   // LDS.64
                mma_f16(acc[nt], a, w.x, w.y);
            }
        }
    }

    // epilogue: scatter-add accumulators into g_msg
    int d0 = ed_s[row0];
    int d1 = ed_s[row0 + 8];
#pragma unroll
    for (int nt = 0; nt < 8; nt++) {
        int col = nt * 8 + jc;
        if (d0 >= 0) {
            atomicAdd(&g_msg[d0 * 64 + col],     acc[nt][0]);
            atomicAdd(&g_msg[d0 * 64 + col + 1], acc[nt][1]);
        }
        if (d1 >= 0) {
            atomicAdd(&g_msg[d1 * 64 + col],     acc[nt][2]);
            atomicAdd(&g_msg[d1 * 64 + col + 1], acc[nt][3]);
        }
    }
}

// ---------------- node update: h = selu(msg @ Wu + bu + h) ----------------
__global__ void __launch_bounds__(256) k_update(const float* __restrict__ Wu,
                                                const float* __restrict__ bu) {
    __shared__ float s_w[64 * 64];
    __shared__ float s_m[16 * 64];
    int t = threadIdx.x;
    int n0 = blockIdx.x * 16;
    for (int idx = t; idx < 4096; idx += 256) s_w[idx] = Wu[idx];
    for (int idx = t; idx < 1024; idx += 256) s_m[idx] = g_msg[n0 * 64 + idx];
    __syncthreads();

    int i = t & 63;
    int bg = t >> 6;
    float bv = bu[i];
#pragma unroll
    for (int rep = 0; rep < 4; rep++) {
        int nn = bg * 4 + rep;
        int n = n0 + nn;
        float y = bv + g_h[n * 64 + i];
#pragma unroll
        for (int k = 0; k < 64; k++) y = fmaf(s_m[nn * 64 + k], s_w[k * 64 + i], y);
        g_h[n * 64 + i] = selu_f(y);
    }
}

// ---------------- embed + readout activation + graph segment-sum ----------------
__global__ void __launch_bounds__(256) k_embed_act(const float* __restrict__ Wae,
                                                   const float* __restrict__ bae,
                                                   const float* __restrict__ WR,
                                                   const float* __restrict__ bR,
                                                   const int* __restrict__ gid) {
    __shared__ float s_w1[4096];
    __shared__ float s_w2[4096];
    __shared__ float s_h[1024];
    __shared__ float s_ae[1024];
    int t = threadIdx.x;
    int n0 = blockIdx.x * 16;
    for (int idx = t; idx < 4096; idx += 256) { s_w1[idx] = Wae[idx]; s_w2[idx] = WR[idx]; }
    for (int idx = t; idx < 1024; idx += 256) s_h[idx] = g_h[n0 * 64 + idx];
    __syncthreads();

    int i = t & 63;
    int bg = t >> 6;
    float b1 = bae[i];
#pragma unroll
    for (int rep = 0; rep < 4; rep++) {
        int nn = bg * 4 + rep;
        float y = b1;
#pragma unroll
        for (int k = 0; k < 64; k++) y = fmaf(s_h[nn * 64 + k], s_w1[k * 64 + i], y);
        s_ae[nn * 64 + i] = y;
    }
    __syncthreads();

    float b2 = bR[i];
#pragma unroll
    for (int rep = 0; rep < 4; rep++) {
        int nn = bg * 4 + rep;
        float y = b2;
#pragma unroll
        for (int k = 0; k < 64; k++) y = fmaf(s_ae[nn * 64 + k], s_w2[k * 64 + i], y);
        float act = selu_f(y);
        int g = gid[n0 + nn];
        atomicAdd(&g_gsum[g * 64 + i], act);
    }
}

// ---------------- head ----------------
__global__ void k_head(const float* __restrict__ Wmlp, const float* __restrict__ bmlp,
                       const float* __restrict__ Wout, const float* __restrict__ bout,
                       float* __restrict__ out) {
    __shared__ float s_ge[64];
    __shared__ float s_mo[64];
    int b = blockIdx.x, t = threadIdx.x;
    s_ge[t] = tanhf(g_gsum[b * 64 + t]);
    __syncthreads();
    float y = bmlp[t];
#pragma unroll
    for (int k = 0; k < 64; k++) y = fmaf(s_ge[k], Wmlp[k * 64 + t], y);
    s_mo[t] = fmaxf(y, 0.f) * Wout[t];
    __syncthreads();
    if (t < 32) {
        float v = s_mo[t] + s_mo[t + 32];
#pragma unroll
        for (int o = 16; o > 0; o >>= 1) v += __shfl_down_sync(0xffffffffu, v, o);
        if (t == 0) out[b] = v + bout[0];
    }
}

// ---------------- launch ----------------
extern "C" void kernel_launch(void* const* d_in, const int* in_sizes, int n_in,
                              void* d_out, int out_size) {
    (void)in_sizes; (void)n_in; (void)out_size;
    const float* nf    = (const float*)d_in[0];
    const float* ef    = (const float*)d_in[1];
    const int*   edom  = (const int*)d_in[2];
    const int*   erng  = (const int*)d_in[3];
    const int*   gid   = (const int*)d_in[4];
    const float* Wm    = (const float*)d_in[5];
    const float* bm    = (const float*)d_in[6];
    const float* Ew    = (const float*)d_in[7];
    const float* Wu0   = (const float*)d_in[8];
    const float* bu0   = (const float*)d_in[9];
    const float* Wu1   = (const float*)d_in[10];
    const float* bu1   = (const float*)d_in[11];
    const float* Wae   = (const float*)d_in[12];
    const float* bae   = (const float*)d_in[13];
    const float* WR    = (const float*)d_in[14];
    const float* bR    = (const float*)d_in[15];
    const float* Wmlp  = (const float*)d_in[16];
    const float* bmlp  = (const float*)d_in[17];
    const float* Wout  = (const float*)d_in[18];
    const float* bout  = (const float*)d_in[19];
    float* out = (float*)d_out;

    cudaFuncSetAttribute(k_msg, cudaFuncAttributeMaxDynamicSharedMemorySize, S2_TOTAL);

    // prep
    k_init_h<<<(N_NODES * H + 255) / 256, 256>>>(nf);
    k_mlp<<<(N_EDGES * H + 255) / 256, 256>>>(ef, Wm, bm);
    k_prep_wpack<<<(CHUNKS * 8 * 8 * 32 + 255) / 256, 256>>>(Ew);

    // message passing step 1
    k_zero_msg<<<(N_NODES * H + 255) / 256, 256>>>();
    k_msg<<<N_TILES, 256, S2_TOTAL>>>(erng, edom);
    k_update<<<N_NODES / 16, 256>>>(Wu0, bu0);

    // message passing step 2
    k_zero_msg<<<(N_NODES * H + 255) / 256, 256>>>();
    k_msg<<<N_TILES, 256, S2_TOTAL>>>(erng, edom);
    k_update<<<N_NODES / 16, 256>>>(Wu1, bu1);

    // readout
    k_zero_gsum<<<(B_GRAPH * H + 255) / 256, 256>>>();
    k_embed_act<<<N_NODES / 16, 256>>>(Wae, bae, WR, bR, gid);
    k_head<<<B_GRAPH, 64>>>(Wmlp, bmlp, Wout, bout, out);
}